// round 15
// baseline (speedup 1.0000x reference)
#include <cuda_runtime.h>
#include <cuda_fp16.h>
#include <cstdint>

#define K_DIM   784
#define KPAD    832
#define H_DIM   1024
#define O_DIM   10
#define B_SIZE  128
#define T_STEPS 200
#define M_TOTAL (B_SIZE * T_STEPS)
#define BETA    0.95f
#define LO_SCALE 2048.0f
#define LO_INV  (1.0f / 2048.0f)

#define E_TOT   4.1e-5f
#define MAXF    1024
#define H_HMMA  576                 // [0,576) HMMA certified; [576,1024) FFMA2 bitwise

// ---- HMMA path tiling (R13) ----
#define BM 128
#define BN 64
#define BK 32
#define NCH (KPAD / BK)
#define ROWB 80
#define A_MAT_BYTES (BM * ROWB)
#define B_MAT_BYTES (BN * ROWB)
#define OFF_AHI 0
#define OFF_ALO (A_MAT_BYTES)
#define OFF_BHI (2 * A_MAT_BYTES)
#define OFF_BLO (2 * A_MAT_BYTES + B_MAT_BYTES)
#define STAGE_BYTES (2 * A_MAT_BYTES + 2 * B_MAT_BYTES)
#define NSTAGE 3
#define SMEM_TOTAL (NSTAGE * STAGE_BYTES)     // 92160

// ---- FFMA2 path tiling: 128 x 64, acc[4][4] ----
#define BMf 128
#define BNf 64
#define BKf 16
#define KTf (K_DIM / BKf)           // 49

#define XS_WORDS (784 * 33)
#define FILL_SMEM (XS_WORDS * 4)

typedef unsigned long long ull;

__device__ float    g_cur1[(size_t)M_TOTAL * H_DIM];
__device__ __half   g_Ahi[(size_t)M_TOTAL * KPAD];
__device__ __half   g_Aslo[(size_t)M_TOTAL * KPAD];
__device__ __half   g_Bhi[(size_t)H_HMMA * KPAD];
__device__ __half   g_Bslo[(size_t)H_HMMA * KPAD];
__device__ unsigned g_spk[(size_t)M_TOTAL * (H_DIM / 32)];
__device__ float    g_cur2T[(size_t)O_DIM * M_TOTAL];
__device__ int      g_flagcnt[B_SIZE];
__device__ unsigned short g_flaglist[B_SIZE * MAXF];

// ---------------- helpers ----------------
__device__ __forceinline__ uint32_t smem_u32(const void* p) {
    uint32_t a;
    asm("{ .reg .u64 t; cvta.to.shared.u64 t, %1; cvt.u32.u64 %0, t; }" : "=r"(a) : "l"(p));
    return a;
}
__device__ __forceinline__ void cp_async16(uint32_t dst, const void* src) {
    asm volatile("cp.async.cg.shared.global [%0], [%1], 16;" :: "r"(dst), "l"(src) : "memory");
}
__device__ __forceinline__ void ldsm_x4(uint32_t (&r)[4], uint32_t addr) {
    asm volatile("ldmatrix.sync.aligned.m8n8.x4.shared.b16 {%0,%1,%2,%3}, [%4];"
                 : "=r"(r[0]), "=r"(r[1]), "=r"(r[2]), "=r"(r[3]) : "r"(addr));
}
__device__ __forceinline__ void mma16816(float (&d)[4], const uint32_t (&a)[4],
                                         const uint32_t b0, const uint32_t b1) {
    asm volatile("mma.sync.aligned.m16n8k16.row.col.f32.f16.f16.f32 "
                 "{%0,%1,%2,%3}, {%4,%5,%6,%7}, {%8,%9}, {%0,%1,%2,%3};"
                 : "+f"(d[0]), "+f"(d[1]), "+f"(d[2]), "+f"(d[3])
                 : "r"(a[0]), "r"(a[1]), "r"(a[2]), "r"(a[3]), "r"(b0), "r"(b1));
}
__device__ __forceinline__ ull ffma2(ull a, ull b, ull c) {
    ull d;
    asm("fma.rn.f32x2 %0, %1, %2, %3;" : "=l"(d) : "l"(a), "l"(b), "l"(c));
    return d;
}
__device__ __forceinline__ void unpack2(ull v, float& x, float& y) {
    asm("mov.b64 {%0, %1}, %2;" : "=f"(x), "=f"(y) : "l"(v));
}
#define SWZA(ch) ((ch) ^ ((ch) >> 3))

// ---------------------------------------------------------------------------
// Split: fp32 -> (hi, lo*2048) fp16.
// ---------------------------------------------------------------------------
__global__ void split_kernel(const float* __restrict__ src,
                             __half* __restrict__ hi, __half* __restrict__ slo,
                             int zero_flags) {
    if (zero_flags && blockIdx.x == 0 && blockIdx.y == 0 && threadIdx.x < B_SIZE)
        g_flagcnt[threadIdx.x] = 0;
    const int col = blockIdx.x * 256 + threadIdx.x;
    const size_t row = blockIdx.y;
    if (col >= KPAD) return;
    float v = (col < K_DIM) ? src[row * K_DIM + col] : 0.0f;
    __half h = __float2half_rn(v);
    float r = v - __half2float(h);
    const size_t oi = row * KPAD + col;
    hi[oi]  = h;
    slo[oi] = __float2half_rn(r * LO_SCALE);
}

// ---------------------------------------------------------------------------
// HMMA sub-GEMM: columns [0, H_HMMA).
// ---------------------------------------------------------------------------
__device__ void gemm_hmma_body(char* smem, int bmi, int bni,
                               const float* __restrict__ bias) {
    const uint32_t sb = smem_u32(smem);
    const int tid  = threadIdx.x;
    const int lane = tid & 31;
    const int wid  = tid >> 5;
    const int wm   = wid & 3;
    const int wn   = wid >> 2;
    const int bm   = bmi * BM;
    const int bn   = bni * BN;

    auto load_stage = [&](int c) {
        const uint32_t base = sb + (uint32_t)(c % NSTAGE) * STAGE_BYTES;
        const int kc = c * BK;
        #pragma unroll
        for (int i = tid; i < BM * 4; i += 256) {
            const int r = i >> 2, ch = i & 3;
            const uint32_t doff = (uint32_t)r * ROWB + ch * 16;
            const size_t gsrc = (size_t)(bm + r) * KPAD + kc + ch * 8;
            cp_async16(base + OFF_AHI + doff, g_Ahi  + gsrc);
            cp_async16(base + OFF_ALO + doff, g_Aslo + gsrc);
        }
        #pragma unroll
        for (int i = tid; i < BN * 4; i += 256) {
            const int r = i >> 2, ch = i & 3;
            const uint32_t doff = (uint32_t)r * ROWB + ch * 16;
            const size_t gsrc = (size_t)(bn + r) * KPAD + kc + ch * 8;
            cp_async16(base + OFF_BHI + doff, g_Bhi  + gsrc);
            cp_async16(base + OFF_BLO + doff, g_Bslo + gsrc);
        }
        asm volatile("cp.async.commit_group;" ::: "memory");
    };

    load_stage(0); load_stage(1);

    const uint32_t aoff0 = (uint32_t)(wm * 32 +  0 + (lane & 15)) * ROWB + ((lane >> 4) << 4);
    const uint32_t aoff1 = (uint32_t)(wm * 32 + 16 + (lane & 15)) * ROWB + ((lane >> 4) << 4);
    const uint32_t boff0 = (uint32_t)(wn * 32 +  0 + (lane & 7) + ((lane >> 4) << 3)) * ROWB
                         + ((lane & 8) ? 16u : 0u);
    const uint32_t boff1 = (uint32_t)(wn * 32 + 16 + (lane & 7) + ((lane >> 4) << 3)) * ROWB
                         + ((lane & 8) ? 16u : 0u);

    float accm[2][4][4], accc[2][4][4];
    #pragma unroll
    for (int i = 0; i < 2; i++)
        #pragma unroll
        for (int j = 0; j < 4; j++)
            #pragma unroll
            for (int k = 0; k < 4; k++) { accm[i][j][k] = 0.f; accc[i][j][k] = 0.f; }

    for (int c = 0; c < NCH; c++) {
        asm volatile("cp.async.wait_group 1;" ::: "memory");
        __syncthreads();
        if (c + 2 < NCH) load_stage(c + 2);

        const uint32_t base = sb + (uint32_t)(c % NSTAGE) * STAGE_BYTES;
        #pragma unroll
        for (int s = 0; s < 2; s++) {
            const uint32_t ko = s * 32;
            uint32_t ah0[4], ah1[4], al0[4], al1[4];
            uint32_t bh0[4], bh1[4], bl0[4], bl1[4];
            ldsm_x4(ah0, base + OFF_AHI + ko + aoff0);
            ldsm_x4(ah1, base + OFF_AHI + ko + aoff1);
            ldsm_x4(al0, base + OFF_ALO + ko + aoff0);
            ldsm_x4(al1, base + OFF_ALO + ko + aoff1);
            ldsm_x4(bh0, base + OFF_BHI + ko + boff0);
            ldsm_x4(bh1, base + OFF_BHI + ko + boff1);
            ldsm_x4(bl0, base + OFF_BLO + ko + boff0);
            ldsm_x4(bl1, base + OFF_BLO + ko + boff1);

            #pragma unroll
            for (int nt = 0; nt < 4; nt++) {
                const uint32_t* bh = (nt < 2) ? bh0 : bh1;
                const int o = (nt & 1) * 2;
                mma16816(accm[0][nt], ah0, bh[o], bh[o + 1]);
                mma16816(accm[1][nt], ah1, bh[o], bh[o + 1]);
            }
            #pragma unroll
            for (int nt = 0; nt < 4; nt++) {
                const uint32_t* bl = (nt < 2) ? bl0 : bl1;
                const int o = (nt & 1) * 2;
                mma16816(accc[0][nt], ah0, bl[o], bl[o + 1]);
                mma16816(accc[1][nt], ah1, bl[o], bl[o + 1]);
            }
            #pragma unroll
            for (int nt = 0; nt < 4; nt++) {
                const uint32_t* bh = (nt < 2) ? bh0 : bh1;
                const int o = (nt & 1) * 2;
                mma16816(accc[0][nt], al0, bh[o], bh[o + 1]);
                mma16816(accc[1][nt], al1, bh[o], bh[o + 1]);
            }
        }
    }

    #pragma unroll
    for (int mt = 0; mt < 2; mt++) {
        const int r0 = bm + wm * 32 + mt * 16 + (lane >> 2);
        #pragma unroll
        for (int nt = 0; nt < 4; nt++) {
            const int col = bn + wn * 32 + nt * 8 + (lane & 3) * 2;
            const float b0 = bias[col], b1 = bias[col + 1];
            float2 v0, v1;
            v0.x = accm[mt][nt][0] + accc[mt][nt][0] * LO_INV + b0;
            v0.y = accm[mt][nt][1] + accc[mt][nt][1] * LO_INV + b1;
            v1.x = accm[mt][nt][2] + accc[mt][nt][2] * LO_INV + b0;
            v1.y = accm[mt][nt][3] + accc[mt][nt][3] * LO_INV + b1;
            *(float2*)&g_cur1[(size_t)r0 * H_DIM + col]       = v0;
            *(float2*)&g_cur1[(size_t)(r0 + 8) * H_DIM + col] = v1;
        }
    }
}

// ---------------------------------------------------------------------------
// FFMA2 sub-GEMM: columns [H_HMMA, 1024), bitwise fp32, 128x64 tile.
// Per-thread 8m x 4n, acc[4][4] (32 regs). Zero-MOV operand pairing.
// ---------------------------------------------------------------------------
__device__ void gemm_ffma2_body(char* smem, int bmi, int bni,
                                const float* __restrict__ x,
                                const float* __restrict__ w1,
                                const float* __restrict__ bias) {
    float* As = (float*)smem;                     // 8KB swizzled [k][m]
    float* Bd = (float*)(smem + BKf * BMf * 4);   // 8KB duplicated [k][2n]

    const int tid = threadIdx.x;
    const int tr  = tid & 15;          // m-block: rows tr*8..tr*8+7
    const int tc  = tid >> 4;          // n-block: cols tc*4..tc*4+3
    const int bm  = bmi * BMf;
    const int bn  = H_HMMA + bni * BNf;
    const int lr  = tid >> 1;          // A load row 0..127
    const int lk  = (tid & 1) * 8;     // A load k offset
    const int lrb = tid >> 2;          // B load row 0..63
    const int kb  = (tid & 3) * 4;     // B load k offset 0,4,8,12
    const int par = tid & 1;
    const int axor = (lk >> 3) * 16;

    const int a_st_base = SWZA(lr >> 2) * 4 + (lr & 3);
    const int a_ld_c0   = SWZA(tr * 2) * 4;
    const int a_ld_c1   = SWZA(tr * 2 + 1) * 4;

    const float* ag = x  + (size_t)(bm + lr) * K_DIM + lk;
    const float* bg = w1 + (size_t)(bn + lrb) * K_DIM + kb;

    float4 a0 = *(const float4*)(ag);
    float4 a1 = *(const float4*)(ag + 4);
    float4 b4 = *(const float4*)(bg);

    ull acc[4][4];
    #pragma unroll
    for (int i = 0; i < 4; i++)
        #pragma unroll
        for (int j = 0; j < 4; j++) acc[i][j] = 0ULL;

    for (int t = 0; t < KTf; t++) {
        __syncthreads();
        {
            const float av[8] = {a0.x, a0.y, a0.z, a0.w, a1.x, a1.y, a1.z, a1.w};
            #pragma unroll
            for (int i = 0; i < 8; i++)
                As[(lk + i) * BMf + (a_st_base ^ axor)] = av[i];
        }
        {
            const float bv4[4] = {b4.x, b4.y, b4.z, b4.w};
            #pragma unroll
            for (int i = 0; i < 4; i++) {
                float* p = &Bd[(kb + i) * (BNf * 2) + 2 * lrb];
                p[par]     = bv4[i];
                p[1 - par] = bv4[i];
            }
        }
        __syncthreads();

        if (t + 1 < KTf) {
            const float* an  = ag + (size_t)(t + 1) * BKf;
            const float* bn_ = bg + (size_t)(t + 1) * BKf;
            a0 = *(const float4*)(an);
            a1 = *(const float4*)(an + 4);
            b4 = *(const float4*)(bn_);
        }

        #pragma unroll
        for (int k = 0; k < BKf; k++) {
            const int kxor = (k >> 3) * 16;
            const ulonglong2 apA = *(const ulonglong2*)&As[k * BMf + (a_ld_c0 ^ kxor)];
            const ulonglong2 apB = *(const ulonglong2*)&As[k * BMf + (a_ld_c1 ^ kxor)];
            const float* bk = &Bd[k * (BNf * 2) + tc * 8];
            const ulonglong2 bq0 = *(const ulonglong2*)(bk);       // (b0,b0),(b1,b1)
            const ulonglong2 bq1 = *(const ulonglong2*)(bk + 4);   // (b2,b2),(b3,b3)

            const ull ap[4] = {apA.x, apA.y, apB.x, apB.y};
            const ull bp[4] = {bq0.x, bq0.y, bq1.x, bq1.y};
            #pragma unroll
            for (int mp = 0; mp < 4; mp++)
                #pragma unroll
                for (int j = 0; j < 4; j++)
                    acc[mp][j] = ffma2(ap[mp], bp[j], acc[mp][j]);
        }
    }

    const int colb = bn + tc * 4;
    float bv[4];
    #pragma unroll
    for (int j = 0; j < 4; j++) bv[j] = bias[colb + j];

    #pragma unroll
    for (int mp = 0; mp < 4; mp++) {
        float r0[4], r1[4];
        #pragma unroll
        for (int j = 0; j < 4; j++) {
            float lo, hi;
            unpack2(acc[mp][j], lo, hi);
            r0[j] = lo + bv[j];
            r1[j] = hi + bv[j];
        }
        const int row = bm + tr * 8 + mp * 2;
        *(float4*)&g_cur1[(size_t)row * H_DIM + colb]       = make_float4(r0[0], r0[1], r0[2], r0[3]);
        *(float4*)&g_cur1[(size_t)(row + 1) * H_DIM + colb] = make_float4(r1[0], r1[1], r1[2], r1[3]);
    }
}

// ---------------------------------------------------------------------------
// Dual-pipe GEMM: per 16-CTA slab: 9 HMMA + 7 FFMA2, interleaved for mix.
// ---------------------------------------------------------------------------
__global__ __launch_bounds__(256, 2) void gemm1_dual(
    const float* __restrict__ x, const float* __restrict__ w1,
    const float* __restrict__ bias) {
    extern __shared__ char smem[];
    const int slab = blockIdx.x >> 4;     // 0..199 (bm index)
    const int p    = blockIdx.x & 15;
    if (p >= 14 || (p & 1) == 0) {
        const int bni = (p < 14) ? (p >> 1) : (7 + (p - 14));   // 0..8
        gemm_hmma_body(smem, slab, bni, bias);
    } else {
        const int bni = p >> 1;                                  // 0..6
        gemm_ffma2_body(smem, slab, bni, x, w1, bias);
    }
}

// ---------------------------------------------------------------------------
// Phase A + certification (flags only h < H_HMMA).
// ---------------------------------------------------------------------------
__global__ __launch_bounds__(256) void phaseA_flag() {
    const int gid = blockIdx.x * 256 + threadIdx.x;
    const int b = gid >> 10;
    const int h = gid & 1023;
    const int lane = threadIdx.x & 31;

    const float* cp = g_cur1 + (size_t)b * T_STEPS * H_DIM + h;
    unsigned* sp = g_spk + (size_t)b * T_STEPS * 32 + (h >> 5);

    float mem = 0.f, spk = 0.f, e = 0.f;
    bool flag = false;

    float cb[4];
    #pragma unroll
    for (int i = 0; i < 4; i++) cb[i] = cp[(size_t)i * H_DIM];

    for (int t0 = 0; t0 < T_STEPS; t0 += 4) {
        float cn[4] = {0.f, 0.f, 0.f, 0.f};
        if (t0 + 4 < T_STEPS) {
            #pragma unroll
            for (int i = 0; i < 4; i++)
                cn[i] = cp[(size_t)(t0 + 4 + i) * H_DIM];
        }
        #pragma unroll
        for (int i = 0; i < 4; i++) {
            mem = fmaf(BETA, mem, cb[i]) - spk;
            e   = fmaf(BETA, e, E_TOT);
            flag |= (fabsf(mem - 1.0f) <= e);
            const bool up = mem > 1.0f;
            spk = up ? 1.0f : 0.0f;
            const unsigned bal = __ballot_sync(0xffffffffu, up);
            if (lane == 0) sp[(size_t)(t0 + i) * 32] = bal;
        }
        #pragma unroll
        for (int i = 0; i < 4; i++) cb[i] = cn[i];
    }
    if (flag && h < H_HMMA) {
        int idx = atomicAdd(&g_flagcnt[b], 1);
        g_flaglist[b * MAXF + idx] = (unsigned short)h;
    }
}

// ---------------------------------------------------------------------------
// repair_fill / rescan: exact strict-k fp32 repair of flagged (b,h).
// ---------------------------------------------------------------------------
__global__ __launch_bounds__(256) void repair_fill(
    const float* __restrict__ x, const float* __restrict__ w1,
    const float* __restrict__ b1)
{
    extern __shared__ float Xs[];
    const int b  = blockIdx.x;
    const int Hf = g_flagcnt[b];
    if (Hf == 0) return;
    const int t0   = blockIdx.y * 32;
    const int tid  = threadIdx.x;
    const int warp = tid >> 5;
    const int lane = tid & 31;

    for (int i = tid; i < 32 * 196; i += 256) {
        const int trow = i / 196, kq = i % 196;
        float4 v = make_float4(0.f, 0.f, 0.f, 0.f);
        if (t0 + trow < T_STEPS)
            v = *(const float4*)&x[((size_t)b * T_STEPS + t0 + trow) * K_DIM + kq * 4];
        Xs[(kq * 4 + 0) * 33 + trow] = v.x;
        Xs[(kq * 4 + 1) * 33 + trow] = v.y;
        Xs[(kq * 4 + 2) * 33 + trow] = v.z;
        Xs[(kq * 4 + 3) * 33 + trow] = v.w;
    }
    __syncthreads();

    const int t = t0 + lane;
    for (int fi = warp; fi < Hf; fi += 8) {
        const int h = g_flaglist[b * MAXF + fi];
        const float* wr = w1 + (size_t)h * K_DIM;
        float acc = 0.f;
        #pragma unroll 4
        for (int k0 = 0; k0 < K_DIM; k0 += 8) {
            const float4 w0 = *(const float4*)(wr + k0);
            const float4 w4 = *(const float4*)(wr + k0 + 4);
            acc = fmaf(Xs[(k0 + 0) * 33 + lane], w0.x, acc);
            acc = fmaf(Xs[(k0 + 1) * 33 + lane], w0.y, acc);
            acc = fmaf(Xs[(k0 + 2) * 33 + lane], w0.z, acc);
            acc = fmaf(Xs[(k0 + 3) * 33 + lane], w0.w, acc);
            acc = fmaf(Xs[(k0 + 4) * 33 + lane], w4.x, acc);
            acc = fmaf(Xs[(k0 + 5) * 33 + lane], w4.y, acc);
            acc = fmaf(Xs[(k0 + 6) * 33 + lane], w4.z, acc);
            acc = fmaf(Xs[(k0 + 7) * 33 + lane], w4.w, acc);
        }
        if (t < T_STEPS)
            g_cur1[((size_t)b * T_STEPS + t) * H_DIM + h] = acc + b1[h];
    }
}

__global__ __launch_bounds__(256) void repair_rescan() {
    const int id = blockIdx.x * 256 + threadIdx.x;
    const int b  = id >> 10;
    const int fi = id & (MAXF - 1);
    if (b >= B_SIZE || fi >= g_flagcnt[b]) return;

    const int h = g_flaglist[b * MAXF + fi];
    const float* cp = g_cur1 + (size_t)b * T_STEPS * H_DIM + h;
    const unsigned mask = 1u << (h & 31);
    float mem = 0.f, spk = 0.f;
    for (int t = 0; t < T_STEPS; t++) {
        mem = fmaf(BETA, mem, cp[(size_t)t * H_DIM]) - spk;
        const bool up = mem > 1.0f;
        spk = up ? 1.0f : 0.0f;
        unsigned* wp = &g_spk[((size_t)b * T_STEPS + t) * 32 + (h >> 5)];
        if (up) atomicOr(wp, mask);
        else    atomicAnd(wp, ~mask);
    }
}

// ---------------------------------------------------------------------------
// Phase B / Phase C.
// ---------------------------------------------------------------------------
__global__ __launch_bounds__(256) void phaseB_kernel(const float* __restrict__ w2) {
    __shared__ float w2s[H_DIM * O_DIM];
    for (int i = threadIdx.x; i < H_DIM * O_DIM; i += 256) {
        const int o = i / H_DIM, h = i % H_DIM;
        w2s[h * O_DIM + o] = w2[i];
    }
    __syncthreads();

    const int warp = blockIdx.x * 8 + (threadIdx.x >> 5);
    const int row  = warp * 32 + (threadIdx.x & 31);

    float acc[O_DIM];
    #pragma unroll
    for (int o = 0; o < O_DIM; o++) acc[o] = 0.f;

    const unsigned* sw = g_spk + (size_t)row * 32;
    for (int wb = 0; wb < 32; wb++) {
        const unsigned bits = sw[wb];
        #pragma unroll 8
        for (int j = 0; j < 32; j++) {
            const float f = ((bits >> j) & 1u) ? 1.0f : 0.0f;
            const float* wp = &w2s[(wb * 32 + j) * O_DIM];
            #pragma unroll
            for (int o = 0; o < O_DIM; o++)
                acc[o] = fmaf(f, wp[o], acc[o]);
        }
    }
    #pragma unroll
    for (int o = 0; o < O_DIM; o++)
        g_cur2T[(size_t)o * M_TOTAL + row] = acc[o];
}

__global__ void phaseC_kernel(const float* __restrict__ b2,
                              float* __restrict__ out_spk,
                              float* __restrict__ out_mem) {
    const int id = blockIdx.x * 32 + threadIdx.x;
    if (id >= B_SIZE * O_DIM) return;
    const int b = id / O_DIM;
    const int o = id % O_DIM;

    const float bias = b2[o];
    const float* cp = g_cur2T + (size_t)o * M_TOTAL + (size_t)b * T_STEPS;
    float* os = out_spk + (size_t)b * T_STEPS * O_DIM + o;
    float* om = out_mem + (size_t)b * T_STEPS * O_DIM + o;

    float mem = 0.f, spk = 0.f;
    for (int t0 = 0; t0 < T_STEPS; t0 += 8) {
        const float4 v0 = *(const float4*)(cp + t0);
        const float4 v1 = *(const float4*)(cp + t0 + 4);
        const float c[8] = {v0.x, v0.y, v0.z, v0.w, v1.x, v1.y, v1.z, v1.w};
        #pragma unroll
        for (int i = 0; i < 8; i++) {
            mem = fmaf(BETA, mem, c[i] + bias) - spk;
            spk = (mem > 1.0f) ? 1.0f : 0.0f;
            os[(size_t)(t0 + i) * O_DIM] = spk;
            om[(size_t)(t0 + i) * O_DIM] = mem;
        }
    }
}

// ---------------------------------------------------------------------------
extern "C" void kernel_launch(void* const* d_in, const int* in_sizes, int n_in,
                              void* d_out, int out_size)
{
    const float* x  = (const float*)d_in[0];
    const float* w1 = (const float*)d_in[1];
    const float* b1 = (const float*)d_in[2];
    const float* w2 = (const float*)d_in[3];
    const float* b2 = (const float*)d_in[4];
    float* out = (float*)d_out;

    cudaFuncSetAttribute(gemm1_dual, cudaFuncAttributeMaxDynamicSharedMemorySize, SMEM_TOTAL);
    cudaFuncSetAttribute(repair_fill, cudaFuncAttributeMaxDynamicSharedMemorySize, FILL_SMEM);

    __half *ahi, *aslo, *bhi, *bslo;
    cudaGetSymbolAddress((void**)&ahi,  g_Ahi);
    cudaGetSymbolAddress((void**)&aslo, g_Aslo);
    cudaGetSymbolAddress((void**)&bhi,  g_Bhi);
    cudaGetSymbolAddress((void**)&bslo, g_Bslo);

    dim3 gs((KPAD + 255) / 256, M_TOTAL);
    split_kernel<<<gs, 256>>>(x, ahi, aslo, 0);
    dim3 gw((KPAD + 255) / 256, H_HMMA);          // only HMMA columns need splits
    split_kernel<<<gw, 256>>>(w1, bhi, bslo, 1);

    gemm1_dual<<<3200, 256, SMEM_TOTAL>>>(x, w1, b1);

    phaseA_flag<<<(B_SIZE * H_DIM) / 256, 256>>>();
    repair_fill<<<dim3(B_SIZE, (T_STEPS + 31) / 32), 256, FILL_SMEM>>>(x, w1, b1);
    repair_rescan<<<(B_SIZE * MAXF) / 256, 256>>>();

    phaseB_kernel<<<M_TOTAL / 256, 256>>>(w2);
    phaseC_kernel<<<(B_SIZE * O_DIM + 31) / 32, 32>>>(
        b2, out, out + (size_t)B_SIZE * T_STEPS * O_DIM);
}

// round 16
// speedup vs baseline: 1.3202x; 1.3202x over previous
#include <cuda_runtime.h>
#include <cuda_fp16.h>
#include <cstdint>

#define K_DIM   784
#define H_DIM   1024
#define O_DIM   10
#define B_SIZE  128
#define T_STEPS 200
#define M_TOTAL (B_SIZE * T_STEPS)
#define BETA    0.95f
#define LO_SCALE 2048.0f
#define LO_INV  (1.0f / 2048.0f)

#define E_TOT   4.1e-5f
#define MAXF    1024

// GEMM tiling: BK=16, no K padding, 4-stage pipeline, 2 CTA/SM
#define BM 128
#define BN 64
#define BK 16
#define NCH (K_DIM / BK)           // 49
#define ROWB 48                    // 32B data + 16B pad (conflict-free ldmatrix)
#define A_MAT_BYTES (BM * ROWB)    // 6144
#define B_MAT_BYTES (BN * ROWB)    // 3072
#define OFF_AHI 0
#define OFF_ALO (A_MAT_BYTES)
#define OFF_BHI (2 * A_MAT_BYTES)
#define OFF_BLO (2 * A_MAT_BYTES + B_MAT_BYTES)
#define STAGE_BYTES (2 * A_MAT_BYTES + 2 * B_MAT_BYTES)   // 18432
#define NSTAGE 4
#define SMEM_TOTAL (NSTAGE * STAGE_BYTES)                 // 73728

#define XS_WORDS (784 * 33)
#define FILL_SMEM (XS_WORDS * 4)

__device__ float    g_cur1[(size_t)M_TOTAL * H_DIM];
__device__ __half   g_Ahi[(size_t)M_TOTAL * K_DIM];
__device__ __half   g_Aslo[(size_t)M_TOTAL * K_DIM];
__device__ __half   g_Bhi[(size_t)H_DIM * K_DIM];
__device__ __half   g_Bslo[(size_t)H_DIM * K_DIM];
__device__ unsigned g_spk[(size_t)M_TOTAL * (H_DIM / 32)];
__device__ int      g_flagcnt[B_SIZE];
__device__ unsigned short g_flaglist[B_SIZE * MAXF];

// ---------------- helpers ----------------
__device__ __forceinline__ uint32_t smem_u32(const void* p) {
    uint32_t a;
    asm("{ .reg .u64 t; cvta.to.shared.u64 t, %1; cvt.u32.u64 %0, t; }" : "=r"(a) : "l"(p));
    return a;
}
__device__ __forceinline__ void cp_async16(uint32_t dst, const void* src) {
    asm volatile("cp.async.cg.shared.global [%0], [%1], 16;" :: "r"(dst), "l"(src) : "memory");
}
__device__ __forceinline__ void ldsm_x4(uint32_t (&r)[4], uint32_t addr) {
    asm volatile("ldmatrix.sync.aligned.m8n8.x4.shared.b16 {%0,%1,%2,%3}, [%4];"
                 : "=r"(r[0]), "=r"(r[1]), "=r"(r[2]), "=r"(r[3]) : "r"(addr));
}
__device__ __forceinline__ void mma16816(float (&d)[4], const uint32_t (&a)[4],
                                         const uint32_t b0, const uint32_t b1) {
    asm volatile("mma.sync.aligned.m16n8k16.row.col.f32.f16.f16.f32 "
                 "{%0,%1,%2,%3}, {%4,%5,%6,%7}, {%8,%9}, {%0,%1,%2,%3};"
                 : "+f"(d[0]), "+f"(d[1]), "+f"(d[2]), "+f"(d[3])
                 : "r"(a[0]), "r"(a[1]), "r"(a[2]), "r"(a[3]), "r"(b0), "r"(b1));
}

// ---------------------------------------------------------------------------
// Split: fp32 -> (hi, lo*2048) fp16. No padding (K exact).
// ---------------------------------------------------------------------------
__global__ void split_kernel(const float* __restrict__ src,
                             __half* __restrict__ hi, __half* __restrict__ slo,
                             int zero_flags) {
    if (zero_flags && blockIdx.x == 0 && blockIdx.y == 0 && threadIdx.x < B_SIZE)
        g_flagcnt[threadIdx.x] = 0;
    const int col = blockIdx.x * 256 + threadIdx.x;
    const size_t row = blockIdx.y;
    if (col >= K_DIM) return;
    const float v = src[row * K_DIM + col];
    const __half h = __float2half_rn(v);
    const float r = v - __half2float(h);
    const size_t oi = row * K_DIM + col;
    hi[oi]  = h;
    slo[oi] = __float2half_rn(r * LO_SCALE);
}

// ---------------------------------------------------------------------------
// Approx GEMM1: cur1 = A@W^T + b1, fp16 hi/lo split mma.sync.
// BK=16, 49 chunks, 12 MMAs/chunk, 4-stage cp.async, 2 CTA/SM.
// ---------------------------------------------------------------------------
__global__ __launch_bounds__(256, 2) void gemm1_mma(const float* __restrict__ bias) {
    extern __shared__ char smem[];
    const uint32_t sb = smem_u32(smem);
    const int tid  = threadIdx.x;
    const int lane = tid & 31;
    const int wid  = tid >> 5;
    const int wm   = wid & 3;
    const int wn   = wid >> 2;
    const int bm   = blockIdx.y * BM;
    const int bn   = blockIdx.x * BN;

    auto load_stage = [&](int c) {
        const uint32_t base = sb + (uint32_t)(c & 3) * STAGE_BYTES;
        const int kc = c * BK;
        // A: 128 rows x 2 chunks -> 256 iterations (1/thread)
        {
            const int r = tid >> 1, ch = tid & 1;
            const uint32_t doff = (uint32_t)r * ROWB + ch * 16;
            const size_t gsrc = (size_t)(bm + r) * K_DIM + kc + ch * 8;
            cp_async16(base + OFF_AHI + doff, g_Ahi  + gsrc);
            cp_async16(base + OFF_ALO + doff, g_Aslo + gsrc);
        }
        // B: 64 rows x 2 chunks -> 128 iterations (tid < 128)
        if (tid < 128) {
            const int r = tid >> 1, ch = tid & 1;
            const uint32_t doff = (uint32_t)r * ROWB + ch * 16;
            const size_t gsrc = (size_t)(bn + r) * K_DIM + kc + ch * 8;
            cp_async16(base + OFF_BHI + doff, g_Bhi  + gsrc);
            cp_async16(base + OFF_BLO + doff, g_Bslo + gsrc);
        }
        asm volatile("cp.async.commit_group;" ::: "memory");
    };

    load_stage(0); load_stage(1); load_stage(2);

    const uint32_t aoff0 = (uint32_t)(wm * 32 +  0 + (lane & 15)) * ROWB + ((lane >> 4) << 4);
    const uint32_t aoff1 = (uint32_t)(wm * 32 + 16 + (lane & 15)) * ROWB + ((lane >> 4) << 4);
    const uint32_t boff0 = (uint32_t)(wn * 32 +  0 + (lane & 7) + ((lane >> 4) << 3)) * ROWB
                         + ((lane & 8) ? 16u : 0u);
    const uint32_t boff1 = (uint32_t)(wn * 32 + 16 + (lane & 7) + ((lane >> 4) << 3)) * ROWB
                         + ((lane & 8) ? 16u : 0u);

    float accm[2][4][4], accc[2][4][4];
    #pragma unroll
    for (int i = 0; i < 2; i++)
        #pragma unroll
        for (int j = 0; j < 4; j++)
            #pragma unroll
            for (int k = 0; k < 4; k++) { accm[i][j][k] = 0.f; accc[i][j][k] = 0.f; }

    for (int c = 0; c < NCH; c++) {
        asm volatile("cp.async.wait_group 2;" ::: "memory");
        __syncthreads();
        if (c + 3 < NCH) load_stage(c + 3);

        const uint32_t base = sb + (uint32_t)(c & 3) * STAGE_BYTES;
        uint32_t ah0[4], ah1[4], al0[4], al1[4];
        uint32_t bh0[4], bh1[4], bl0[4], bl1[4];
        ldsm_x4(ah0, base + OFF_AHI + aoff0);
        ldsm_x4(ah1, base + OFF_AHI + aoff1);
        ldsm_x4(al0, base + OFF_ALO + aoff0);
        ldsm_x4(al1, base + OFF_ALO + aoff1);
        ldsm_x4(bh0, base + OFF_BHI + boff0);
        ldsm_x4(bh1, base + OFF_BHI + boff1);
        ldsm_x4(bl0, base + OFF_BLO + boff0);
        ldsm_x4(bl1, base + OFF_BLO + boff1);

        // grouped by type: hh, then hl, then lh (dependent accc updates spaced)
        #pragma unroll
        for (int nt = 0; nt < 4; nt++) {
            const uint32_t* bh = (nt < 2) ? bh0 : bh1;
            const int o = (nt & 1) * 2;
            mma16816(accm[0][nt], ah0, bh[o], bh[o + 1]);
            mma16816(accm[1][nt], ah1, bh[o], bh[o + 1]);
        }
        #pragma unroll
        for (int nt = 0; nt < 4; nt++) {
            const uint32_t* bl = (nt < 2) ? bl0 : bl1;
            const int o = (nt & 1) * 2;
            mma16816(accc[0][nt], ah0, bl[o], bl[o + 1]);
            mma16816(accc[1][nt], ah1, bl[o], bl[o + 1]);
        }
        #pragma unroll
        for (int nt = 0; nt < 4; nt++) {
            const uint32_t* bh = (nt < 2) ? bh0 : bh1;
            const int o = (nt & 1) * 2;
            mma16816(accc[0][nt], al0, bh[o], bh[o + 1]);
            mma16816(accc[1][nt], al1, bh[o], bh[o + 1]);
        }
    }

    #pragma unroll
    for (int mt = 0; mt < 2; mt++) {
        const int r0 = bm + wm * 32 + mt * 16 + (lane >> 2);
        #pragma unroll
        for (int nt = 0; nt < 4; nt++) {
            const int col = bn + wn * 32 + nt * 8 + (lane & 3) * 2;
            const float b0 = bias[col], b1 = bias[col + 1];
            float2 v0, v1;
            v0.x = accm[mt][nt][0] + accc[mt][nt][0] * LO_INV + b0;
            v0.y = accm[mt][nt][1] + accc[mt][nt][1] * LO_INV + b1;
            v1.x = accm[mt][nt][2] + accc[mt][nt][2] * LO_INV + b0;
            v1.y = accm[mt][nt][3] + accc[mt][nt][3] * LO_INV + b1;
            *(float2*)&g_cur1[(size_t)r0 * H_DIM + col]       = v0;
            *(float2*)&g_cur1[(size_t)(r0 + 8) * H_DIM + col] = v1;
        }
    }
}

// ---------------------------------------------------------------------------
// Phase A + certification flagging; MLP-8 load batching.
// ---------------------------------------------------------------------------
__global__ __launch_bounds__(256) void phaseA_flag() {
    const int gid = blockIdx.x * 256 + threadIdx.x;
    const int b = gid >> 10;
    const int h = gid & 1023;
    const int lane = threadIdx.x & 31;

    const float* cp = g_cur1 + (size_t)b * T_STEPS * H_DIM + h;
    unsigned* sp = g_spk + (size_t)b * T_STEPS * 32 + (h >> 5);

    float mem = 0.f, spk = 0.f, e = 0.f;
    bool flag = false;

    float cb[8];
    #pragma unroll
    for (int i = 0; i < 8; i++) cb[i] = cp[(size_t)i * H_DIM];

    for (int t0 = 0; t0 < T_STEPS; t0 += 8) {
        float cn[8] = {0.f, 0.f, 0.f, 0.f, 0.f, 0.f, 0.f, 0.f};
        if (t0 + 8 < T_STEPS) {
            #pragma unroll
            for (int i = 0; i < 8; i++)
                cn[i] = cp[(size_t)(t0 + 8 + i) * H_DIM];
        }
        #pragma unroll
        for (int i = 0; i < 8; i++) {
            mem = fmaf(BETA, mem, cb[i]) - spk;
            e   = fmaf(BETA, e, E_TOT);
            flag |= (fabsf(mem - 1.0f) <= e);
            const bool up = mem > 1.0f;
            spk = up ? 1.0f : 0.0f;
            const unsigned bal = __ballot_sync(0xffffffffu, up);
            if (lane == 0) sp[(size_t)(t0 + i) * 32] = bal;
        }
        #pragma unroll
        for (int i = 0; i < 8; i++) cb[i] = cn[i];
    }
    if (flag) {
        int idx = atomicAdd(&g_flagcnt[b], 1);
        g_flaglist[b * MAXF + idx] = (unsigned short)h;
    }
}

// ---------------------------------------------------------------------------
// repair_fill: CTA per (b, t0-block); exact strict-k fp32 chains for flagged h.
// ---------------------------------------------------------------------------
__global__ __launch_bounds__(256) void repair_fill(
    const float* __restrict__ x, const float* __restrict__ w1,
    const float* __restrict__ b1)
{
    extern __shared__ float Xs[];
    const int b  = blockIdx.x;
    const int Hf = g_flagcnt[b];
    if (Hf == 0) return;
    const int t0   = blockIdx.y * 32;
    const int tid  = threadIdx.x;
    const int warp = tid >> 5;
    const int lane = tid & 31;

    for (int i = tid; i < 32 * 196; i += 256) {
        const int trow = i / 196, kq = i % 196;
        float4 v = make_float4(0.f, 0.f, 0.f, 0.f);
        if (t0 + trow < T_STEPS)
            v = *(const float4*)&x[((size_t)b * T_STEPS + t0 + trow) * K_DIM + kq * 4];
        Xs[(kq * 4 + 0) * 33 + trow] = v.x;
        Xs[(kq * 4 + 1) * 33 + trow] = v.y;
        Xs[(kq * 4 + 2) * 33 + trow] = v.z;
        Xs[(kq * 4 + 3) * 33 + trow] = v.w;
    }
    __syncthreads();

    const int t = t0 + lane;
    for (int fi = warp; fi < Hf; fi += 8) {
        const int h = g_flaglist[b * MAXF + fi];
        const float* wr = w1 + (size_t)h * K_DIM;
        float acc = 0.f;
        #pragma unroll 4
        for (int k0 = 0; k0 < K_DIM; k0 += 8) {
            const float4 w0 = *(const float4*)(wr + k0);
            const float4 w4 = *(const float4*)(wr + k0 + 4);
            acc = fmaf(Xs[(k0 + 0) * 33 + lane], w0.x, acc);
            acc = fmaf(Xs[(k0 + 1) * 33 + lane], w0.y, acc);
            acc = fmaf(Xs[(k0 + 2) * 33 + lane], w0.z, acc);
            acc = fmaf(Xs[(k0 + 3) * 33 + lane], w0.w, acc);
            acc = fmaf(Xs[(k0 + 4) * 33 + lane], w4.x, acc);
            acc = fmaf(Xs[(k0 + 5) * 33 + lane], w4.y, acc);
            acc = fmaf(Xs[(k0 + 6) * 33 + lane], w4.z, acc);
            acc = fmaf(Xs[(k0 + 7) * 33 + lane], w4.w, acc);
        }
        if (t < T_STEPS)
            g_cur1[((size_t)b * T_STEPS + t) * H_DIM + h] = acc + b1[h];
    }
}

// ---------------------------------------------------------------------------
// rescan: one thread per flagged pair; exact scan, patch bits.
// ---------------------------------------------------------------------------
__global__ __launch_bounds__(256) void repair_rescan() {
    const int id = blockIdx.x * 256 + threadIdx.x;
    const int b  = id >> 10;
    const int fi = id & (MAXF - 1);
    if (b >= B_SIZE || fi >= g_flagcnt[b]) return;

    const int h = g_flaglist[b * MAXF + fi];
    const float* cp = g_cur1 + (size_t)b * T_STEPS * H_DIM + h;
    const unsigned mask = 1u << (h & 31);
    float mem = 0.f, spk = 0.f;
    for (int t = 0; t < T_STEPS; t++) {
        mem = fmaf(BETA, mem, cp[(size_t)t * H_DIM]) - spk;
        const bool up = mem > 1.0f;
        spk = up ? 1.0f : 0.0f;
        unsigned* wp = &g_spk[((size_t)b * T_STEPS + t) * 32 + (h >> 5)];
        if (up) atomicOr(wp, mask);
        else    atomicAnd(wp, ~mask);
    }
}

// ---------------------------------------------------------------------------
// Fused Phase B+C: one CTA per batch. Thread t computes cur2[t][:] (h strictly
// sequential, same op order as before), staged in smem; then 10 lanes run the
// exact mem2 scan and write outputs. Removes the cur2T global round-trip.
// ---------------------------------------------------------------------------
__global__ __launch_bounds__(256) void phaseBC_kernel(
    const float* __restrict__ w2, const float* __restrict__ b2,
    float* __restrict__ out_spk, float* __restrict__ out_mem)
{
    __shared__ float w2s[H_DIM * O_DIM];      // 40 KB
    __shared__ float c2s[T_STEPS * O_DIM];    // 8 KB
    const int b = blockIdx.x;
    const int tid = threadIdx.x;

    for (int i = tid; i < H_DIM * O_DIM; i += 256) {
        const int o = i / H_DIM, h = i % H_DIM;
        w2s[h * O_DIM + o] = w2[i];
    }
    __syncthreads();

    if (tid < T_STEPS) {
        const int row = b * T_STEPS + tid;
        float acc[O_DIM];
        #pragma unroll
        for (int o = 0; o < O_DIM; o++) acc[o] = 0.f;

        const unsigned* sw = g_spk + (size_t)row * 32;
        for (int wb = 0; wb < 32; wb++) {
            const unsigned bits = sw[wb];
            #pragma unroll 8
            for (int j = 0; j < 32; j++) {
                const float f = ((bits >> j) & 1u) ? 1.0f : 0.0f;
                const float* wp = &w2s[(wb * 32 + j) * O_DIM];
                #pragma unroll
                for (int o = 0; o < O_DIM; o++)
                    acc[o] = fmaf(f, wp[o], acc[o]);
            }
        }
        #pragma unroll
        for (int o = 0; o < O_DIM; o++) c2s[tid * O_DIM + o] = acc[o];
    }
    __syncthreads();

    if (tid < O_DIM) {
        const int o = tid;
        const float bias = b2[o];
        float* os = out_spk + (size_t)b * T_STEPS * O_DIM + o;
        float* om = out_mem + (size_t)b * T_STEPS * O_DIM + o;
        float mem = 0.f, spk = 0.f;
        for (int t = 0; t < T_STEPS; t++) {
            const float c = c2s[t * O_DIM + o];
            mem = fmaf(BETA, mem, c + bias) - spk;
            spk = (mem > 1.0f) ? 1.0f : 0.0f;
            os[(size_t)t * O_DIM] = spk;
            om[(size_t)t * O_DIM] = mem;
        }
    }
}

// ---------------------------------------------------------------------------
extern "C" void kernel_launch(void* const* d_in, const int* in_sizes, int n_in,
                              void* d_out, int out_size)
{
    const float* x  = (const float*)d_in[0];
    const float* w1 = (const float*)d_in[1];
    const float* b1 = (const float*)d_in[2];
    const float* w2 = (const float*)d_in[3];
    const float* b2 = (const float*)d_in[4];
    float* out = (float*)d_out;

    cudaFuncSetAttribute(gemm1_mma, cudaFuncAttributeMaxDynamicSharedMemorySize, SMEM_TOTAL);
    cudaFuncSetAttribute(repair_fill, cudaFuncAttributeMaxDynamicSharedMemorySize, FILL_SMEM);

    __half *ahi, *aslo, *bhi, *bslo;
    cudaGetSymbolAddress((void**)&ahi,  g_Ahi);
    cudaGetSymbolAddress((void**)&aslo, g_Aslo);
    cudaGetSymbolAddress((void**)&bhi,  g_Bhi);
    cudaGetSymbolAddress((void**)&bslo, g_Bslo);

    dim3 gs((K_DIM + 255) / 256, M_TOTAL);
    split_kernel<<<gs, 256>>>(x, ahi, aslo, 0);
    dim3 gw((K_DIM + 255) / 256, H_DIM);
    split_kernel<<<gw, 256>>>(w1, bhi, bslo, 1);   // also zeroes g_flagcnt

    dim3 gg(H_DIM / BN, M_TOTAL / BM);             // (16, 200)
    gemm1_mma<<<gg, 256, SMEM_TOTAL>>>(b1);

    phaseA_flag<<<(B_SIZE * H_DIM) / 256, 256>>>();
    repair_fill<<<dim3(B_SIZE, (T_STEPS + 31) / 32), 256, FILL_SMEM>>>(x, w1, b1);
    repair_rescan<<<(B_SIZE * MAXF) / 256, 256>>>();

    phaseBC_kernel<<<B_SIZE, 256>>>(w2, b2, out, out + (size_t)B_SIZE * T_STEPS * O_DIM);
}